// round 1
// baseline (speedup 1.0000x reference)
#include <cuda_runtime.h>

#define BATCH 8
#define LBL 8
#define EDIM 4
#define HT 640
#define WD 640
#define HW (HT*WD)
#define NV4 (HW/4)

typedef unsigned long long u64;
typedef unsigned int u32;

// ---------------- scratch (no allocations allowed) ----------------
__device__ u64   g_occ [BATCH][LBL];           // packed (first<<32)|second
__device__ float g_sumk[BATCH][LBL][EDIM];     // kernel-region emb sums
__device__ float g_cntk[BATCH][LBL];           // kernel-region counts
__device__ float g_agg [BATCH][LBL];           // l_agg numerators
__device__ float g_cntf[BATCH][LBL];           // full-region counts
__device__ float g_mean[BATCH][LBL][EDIM];
__device__ float g_cd  [BATCH][LBL];           // coef_diag
__device__ float g_dr  [BATCH];                // l_dis + l_reg per image
__device__ unsigned char g_lab[BATCH*HW];      // masked labels (u8)

// merge sorted pair (b1<=b2) into packed two-smallest at *p
__device__ __forceinline__ void merge_pair(u64* p, u32 b1, u32 b2){
  u64 old = *p;
  for(;;){
    u32 g1 = (u32)(old>>32), g2 = (u32)old;
    u32 m1, m2;
    if (b1 < g1){ m1 = b1; m2 = (g1 < b2) ? g1 : b2; }
    else        { m1 = g1; m2 = (b1 < g2) ? b1 : g2; }
    if (m1 == g1 && m2 == g2) return;
    u64 nv = ((u64)m1<<32) | (u64)m2;
    u64 prev = atomicCAS(p, old, nv);
    if (prev == old) return;
    old = prev;
  }
}

// ---------------- init (graph replays need per-launch reset) ----------------
__global__ void k_init(){
  int t = blockIdx.x*blockDim.x + threadIdx.x;
  const u64 sent = (((u64)HW)<<32) | (u64)HW;
  if (t < BATCH*LBL){
    ((u64*)g_occ)[t]   = sent;
    ((float*)g_cntk)[t] = 0.f;
    ((float*)g_agg )[t] = 0.f;
    ((float*)g_cntf)[t] = 0.f;
  }
  if (t < BATCH*LBL*EDIM) ((float*)g_sumk)[t] = 0.f;
}

// ---------------- pass A: occurrences + kernel-region sums + label cache ----
__device__ __forceinline__ void procA(int l, int idx, float kf,
    float e0, float e1, float e2, float e3,
    u64* s_occ, float (*s_sum)[EDIM], float* s_cntk){
  if (l > 0){
    u64 cur = s_occ[l];                 // non-atomic guard; values only decrease
    if ((u32)idx < (u32)cur) merge_pair(&s_occ[l], (u32)idx, (u32)HW);
    if (kf > 0.5f){
      atomicAdd(&s_cntk[l], 1.f);
      atomicAdd(&s_sum[l][0], e0);
      atomicAdd(&s_sum[l][1], e1);
      atomicAdd(&s_sum[l][2], e2);
      atomicAdd(&s_sum[l][3], e3);
    }
  }
}

__global__ void __launch_bounds__(256) kA(const float* __restrict__ emb,
                                          const int*   __restrict__ inst,
                                          const float* __restrict__ kern,
                                          const float* __restrict__ tmask){
  const int b   = blockIdx.y;
  const int tid = threadIdx.x;
  __shared__ u64   s_occ[LBL];
  __shared__ float s_sum[LBL][EDIM];
  __shared__ float s_cntk[LBL];
  if (tid < LBL){ s_occ[tid] = (((u64)HW)<<32)|(u64)HW; s_cntk[tid] = 0.f; }
  if (tid < LBL*EDIM) ((float*)s_sum)[tid] = 0.f;
  __syncthreads();

  const float* e0 = emb + (size_t)b*EDIM*HW;
  const int4*   ip = (const int4*)  (inst  + (size_t)b*HW);
  const float4* kp = (const float4*)(kern  + (size_t)b*HW);
  const float4* tp = (const float4*)(tmask + (size_t)b*HW);
  uchar4*       lp = (uchar4*)(g_lab + (size_t)b*HW);

  for (int i = blockIdx.x*blockDim.x + tid; i < NV4; i += gridDim.x*blockDim.x){
    int4   iv = ip[i];
    float4 kv = kp[i];
    float4 tv = tp[i];
    float4 e[EDIM];
    #pragma unroll
    for (int d = 0; d < EDIM; d++)
      e[d] = ((const float4*)(e0 + (size_t)d*HW))[i];

    int l0 = (tv.x > 0.5f) ? iv.x : 0;
    int l1 = (tv.y > 0.5f) ? iv.y : 0;
    int l2 = (tv.z > 0.5f) ? iv.z : 0;
    int l3 = (tv.w > 0.5f) ? iv.w : 0;
    lp[i] = make_uchar4((unsigned char)l0,(unsigned char)l1,
                        (unsigned char)l2,(unsigned char)l3);
    const int base = i*4;
    procA(l0, base+0, kv.x, e[0].x, e[1].x, e[2].x, e[3].x, s_occ, s_sum, s_cntk);
    procA(l1, base+1, kv.y, e[0].y, e[1].y, e[2].y, e[3].y, s_occ, s_sum, s_cntk);
    procA(l2, base+2, kv.z, e[0].z, e[1].z, e[2].z, e[3].z, s_occ, s_sum, s_cntk);
    procA(l3, base+3, kv.w, e[0].w, e[1].w, e[2].w, e[3].w, s_occ, s_sum, s_cntk);
  }
  __syncthreads();
  if (tid < LBL){
    u64 v = s_occ[tid];
    merge_pair(&g_occ[b][tid], (u32)(v>>32), (u32)v);
    float c = s_cntk[tid];
    if (c != 0.f) atomicAdd(&g_cntk[b][tid], c);
  }
  if (tid < LBL*EDIM){
    float v = ((float*)s_sum)[tid];
    if (v != 0.f) atomicAdd(&((float*)g_sumk)[b*LBL*EDIM + tid], v);
  }
}

// ---------------- per-image small math: means, coef, l_dis, l_reg ----------
__global__ void kC(){
  const int b   = blockIdx.x;
  const int tid = threadIdx.x;        // 64 threads
  __shared__ float sm[LBL][EDIM];
  __shared__ float ss[LBL], st[LBL];
  __shared__ float red[64];
  const float diag = sqrtf((float)(HT*HT + WD*WD));

  if (tid < LBL){
    u64 v  = g_occ[b][tid];
    u32 f  = (u32)(v>>32); if (f  > (u32)(HW-1)) f  = HW-1;
    u32 s2 = (u32)v;       if (s2 > (u32)(HW-1)) s2 = HW-1;
    float r0 = (float)(f  / WD), c0 = (float)(f  % WD);
    float r1 = (float)(s2 / WD), c1 = (float)(s2 % WD);
    float cd = 0.f;
    if (tid > 0){
      float dx = r0 - c0, dy = r1 - c1;
      cd = expf(sqrtf(dx*dx + dy*dy) / diag * 0.5f);
    }
    g_cd[b][tid] = cd;
    ss[tid] = r0 + c0;
    st[tid] = r1 + c1;
  }
  if (tid < LBL*EDIM){
    int l = tid / EDIM, d = tid % EDIM;
    float m = 0.f;
    if (l > 0) m = g_sumk[b][l][d] / fmaxf(g_cntk[b][l], 1.f);
    sm[l][d] = m;
    g_mean[b][l][d] = m;
  }
  __syncthreads();

  float acc = 0.f;
  {
    int i = tid / LBL, j = tid % LBL;     // 64 pairs
    if (i != j && i > 0 && j > 0){
      float sq = 0.f;
      #pragma unroll
      for (int d = 0; d < EDIM; d++){ float dd = sm[i][d]-sm[j][d]; sq += dd*dd; }
      float Dn = (sq > 0.f) ? sqrtf(sq) : 0.f;
      float dsp = ss[i]-ss[j], dtp = st[i]-st[j];
      float dp = sqrtf(dsp*dsp + dtp*dtp);
      float coef = 1.f - 20.f*expf(-4.f - 2.5f*dp/diag);
      float x = fmaxf(3.f - coef*Dn, 0.f);    // 2*DD = 3.0
      acc = logf(x*x + 1.f);
    }
  }
  float reg = 0.f;
  if (tid < LBL){
    float sq = 0.f;
    #pragma unroll
    for (int d = 0; d < EDIM; d++) sq += sm[tid][d]*sm[tid][d];
    float n = (sq > 0.f) ? sqrtf(sq) : 0.f;
    reg = logf(n + 1.f);
  }
  red[tid] = acc*(1.f/42.f) + reg*(0.001f/8.f);
  __syncthreads();
  for (int s = 32; s > 0; s >>= 1){
    if (tid < s) red[tid] += red[tid+s];
    __syncthreads();
  }
  if (tid == 0) g_dr[b] = red[0];
}

// ---------------- pass D: per-pixel agg hinge ----------------
__global__ void __launch_bounds__(256) kD(const float* __restrict__ emb){
  const int b   = blockIdx.y;
  const int tid = threadIdx.x;
  __shared__ float sm[LBL][EDIM];
  __shared__ float scd[LBL], sagg[LBL], scnt[LBL];
  if (tid < LBL*EDIM) ((float*)sm)[tid] = ((float*)g_mean)[b*LBL*EDIM + tid];
  if (tid < LBL){ scd[tid] = g_cd[b][tid]; sagg[tid] = 0.f; scnt[tid] = 0.f; }
  __syncthreads();

  const float*  e0 = emb + (size_t)b*EDIM*HW;
  const uchar4* lp = (const uchar4*)(g_lab + (size_t)b*HW);

  for (int i = blockIdx.x*blockDim.x + tid; i < NV4; i += gridDim.x*blockDim.x){
    uchar4 lv = lp[i];
    float4 e[EDIM];
    #pragma unroll
    for (int d = 0; d < EDIM; d++)
      e[d] = ((const float4*)(e0 + (size_t)d*HW))[i];

    #pragma unroll
    for (int j = 0; j < 4; j++){
      int l = (j==0) ? lv.x : (j==1) ? lv.y : (j==2) ? lv.z : lv.w;
      if (l > 0){
        float v0 = (j==0)?e[0].x:(j==1)?e[0].y:(j==2)?e[0].z:e[0].w;
        float v1 = (j==0)?e[1].x:(j==1)?e[1].y:(j==2)?e[1].z:e[1].w;
        float v2 = (j==0)?e[2].x:(j==1)?e[2].y:(j==2)?e[2].z:e[2].w;
        float v3 = (j==0)?e[3].x:(j==1)?e[3].y:(j==2)?e[3].z:e[3].w;
        float d0 = v0 - sm[l][0], d1 = v1 - sm[l][1];
        float d2 = v2 - sm[l][2], d3 = v3 - sm[l][3];
        float sq = d0*d0 + d1*d1 + d2*d2 + d3*d3;
        float dist = (sq > 0.f) ? sqrtf(sq) : 0.f;
        float x = fmaxf(scd[l]*dist - 0.5f, 0.f);
        atomicAdd(&sagg[l], logf(x*x + 1.f));
        atomicAdd(&scnt[l], 1.f);
      }
    }
  }
  __syncthreads();
  if (tid > 0 && tid < LBL){
    float c = scnt[tid];
    if (c != 0.f){
      atomicAdd(&g_agg[b][tid],  sagg[tid]);
      atomicAdd(&g_cntf[b][tid], c);
    }
  }
}

// ---------------- finalize ----------------
__global__ void kE(float* __restrict__ out){
  const int tid = threadIdx.x;
  __shared__ float red[BATCH];
  if (tid < BATCH){
    float s = 0.f;
    #pragma unroll
    for (int l = 1; l < LBL; l++)
      s += g_agg[tid][l] / fmaxf(g_cntf[tid][l], 1.f);
    red[tid] = s*(1.f/7.f) + g_dr[tid];
  }
  __syncthreads();
  if (tid == 0){
    float t = 0.f;
    #pragma unroll
    for (int b = 0; b < BATCH; b++) t += red[b];
    out[0] = t*(1.f/BATCH);
  }
}

extern "C" void kernel_launch(void* const* d_in, const int* in_sizes, int n_in,
                              void* d_out, int out_size){
  const float* emb   = (const float*)d_in[0];
  const int*   inst  = (const int*)  d_in[1];
  const float* kern  = (const float*)d_in[2];
  const float* tmask = (const float*)d_in[3];
  // d_in[4] = bboxes, unused by the reference

  k_init<<<1, 256>>>();
  kA<<<dim3(128, BATCH), 256>>>(emb, inst, kern, tmask);
  kC<<<BATCH, 64>>>();
  kD<<<dim3(128, BATCH), 256>>>(emb);
  kE<<<1, 32>>>((float*)d_out);
}

// round 2
// speedup vs baseline: 1.6612x; 1.6612x over previous
#include <cuda_runtime.h>

#define BATCH 8
#define LBL 8
#define EDIM 4
#define HT 640
#define WD 640
#define HW (HT*WD)
#define NV4 (HW/4)
#define WARPS 8
#define NTHR 256
#define DIAG 905.0966799187808f   // sqrt(640^2+640^2)

typedef unsigned long long u64;
typedef unsigned int u32;

// ---------------- scratch ----------------
__device__ u64   g_occ [BATCH][LBL];        // packed (first<<32)|second
__device__ float g_sumk[BATCH][LBL][EDIM];
__device__ float g_cntk[BATCH][LBL];
__device__ float g_agg [BATCH][LBL];
__device__ float g_cntf[BATCH][LBL];
__device__ float g_dr  [BATCH];             // l_dis + l_reg
__device__ unsigned char g_lab[BATCH*HW];   // masked labels

// merge sorted pair (b1<=b2) into packed two-smallest at *p
__device__ __forceinline__ void merge_pair(u64* p, u32 b1, u32 b2){
  u64 old = *p;
  for(;;){
    u32 g1 = (u32)(old>>32), g2 = (u32)old;
    u32 m1, m2;
    if (b1 < g1){ m1 = b1; m2 = (g1 < b2) ? g1 : b2; }
    else        { m1 = g1; m2 = (b1 < g2) ? b1 : g2; }
    if (m1 == g1 && m2 == g2) return;
    u64 nv = ((u64)m1<<32) | (u64)m2;
    u64 prev = atomicCAS(p, old, nv);
    if (prev == old) return;
    old = prev;
  }
}

// ---------------- init ----------------
__global__ void k_init(){
  int t = blockIdx.x*blockDim.x + threadIdx.x;
  const u64 sent = (((u64)HW)<<32) | (u64)HW;
  if (t < BATCH*LBL){
    ((u64*)g_occ)[t]    = sent;
    ((float*)g_cntk)[t] = 0.f;
    ((float*)g_agg )[t] = 0.f;
    ((float*)g_cntf)[t] = 0.f;
  }
  if (t < BATCH*LBL*EDIM) ((float*)g_sumk)[t] = 0.f;
}

// ---------------- pass A: occurrences + kernel-region sums + label cache ----
__global__ void __launch_bounds__(NTHR) kA(const float* __restrict__ emb,
                                           const int*   __restrict__ inst,
                                           const float* __restrict__ kern,
                                           const float* __restrict__ tmask){
  const int b    = blockIdx.y;
  const int tid  = threadIdx.x;
  const int w    = tid >> 5;
  const int lane = tid & 31;
  __shared__ float s_sum [WARPS][LBL][EDIM][32];   // 32 KB, bank = lane
  __shared__ float s_cntk[WARPS][LBL][32];         //  8 KB
  __shared__ u64   s_occ [LBL];

  for (int i = tid; i < WARPS*LBL*EDIM*32; i += NTHR) ((float*)s_sum )[i] = 0.f;
  for (int i = tid; i < WARPS*LBL*32;      i += NTHR) ((float*)s_cntk)[i] = 0.f;
  if (tid < LBL) s_occ[tid] = (((u64)HW)<<32) | (u64)HW;
  __syncthreads();

  const float* eb = emb + (size_t)b*EDIM*HW;
  const int4*   ip = (const int4*)  (inst  + (size_t)b*HW);
  const float4* kp = (const float4*)(kern  + (size_t)b*HW);
  const float4* tp = (const float4*)(tmask + (size_t)b*HW);
  uchar4*       lp = (uchar4*)(g_lab + (size_t)b*HW);

  float* mysum = &s_sum [w][0][0][lane];   // + l*128 + d*32
  float* mycnt = &s_cntk[w][0][lane];      // + l*32

  for (int i = blockIdx.x*NTHR + tid; i < NV4; i += gridDim.x*NTHR){
    int4   iv = ip[i];
    float4 kv = kp[i];
    float4 tv = tp[i];
    float4 e0 = ((const float4*)(eb        ))[i];
    float4 e1 = ((const float4*)(eb +   HW ))[i];
    float4 e2 = ((const float4*)(eb + 2*HW ))[i];
    float4 e3 = ((const float4*)(eb + 3*HW ))[i];

    int l0 = (tv.x > 0.5f) ? iv.x : 0;
    int l1 = (tv.y > 0.5f) ? iv.y : 0;
    int l2 = (tv.z > 0.5f) ? iv.z : 0;
    int l3 = (tv.w > 0.5f) ? iv.w : 0;
    lp[i] = make_uchar4((unsigned char)l0,(unsigned char)l1,
                        (unsigned char)l2,(unsigned char)l3);
    const int base = i*4;

#define PROC_A(LV, JJ, KF, E0, E1, E2, E3)                                  \
    if (LV > 0){                                                            \
      u32 second = ((const u32*)&s_occ[LV])[0];                             \
      if ((u32)(base+JJ) < second) merge_pair(&s_occ[LV], (u32)(base+JJ), (u32)HW); \
      if (KF > 0.5f){                                                       \
        float* p = mysum + LV*(EDIM*32);                                    \
        p[0]  += E0; p[32] += E1; p[64] += E2; p[96] += E3;                 \
        mycnt[LV*32] += 1.f;                                                \
      }                                                                     \
    }
    PROC_A(l0, 0, kv.x, e0.x, e1.x, e2.x, e3.x)
    PROC_A(l1, 1, kv.y, e0.y, e1.y, e2.y, e3.y)
    PROC_A(l2, 2, kv.z, e0.z, e1.z, e2.z, e3.z)
    PROC_A(l3, 3, kv.w, e0.w, e1.w, e2.w, e3.w)
#undef PROC_A
  }
  __syncthreads();

  if (tid < LBL){
    u64 v = s_occ[tid];
    merge_pair(&g_occ[b][tid], (u32)(v>>32), (u32)v);
  }
  { // 256 threads = 8w * 8l * 4d ; lane-rotated, conflict-free
    int rw = tid>>5, rl = (tid>>2)&7, rd = tid&3;
    float s = 0.f;
    #pragma unroll
    for (int k = 0; k < 32; k++) s += s_sum[rw][rl][rd][(k+tid)&31];
    if (s != 0.f) atomicAdd(&g_sumk[b][rl][rd], s);
  }
  if (tid < 64){
    int rw = tid>>3, rl = tid&7;
    float c = 0.f;
    #pragma unroll
    for (int k = 0; k < 32; k++) c += s_cntk[rw][rl][(k+tid)&31];
    if (c != 0.f) atomicAdd(&g_cntk[b][rl], c);
  }
}

// ---------------- pass D: agg hinge (+ fused small per-image math) ---------
__global__ void __launch_bounds__(NTHR) kD(const float* __restrict__ emb){
  const int b    = blockIdx.y;
  const int tid  = threadIdx.x;
  const int w    = tid >> 5;
  const int lane = tid & 31;
  __shared__ float s_val[WARPS][LBL][32];   // 8 KB
  __shared__ float s_cnt[WARPS][LBL][32];   // 8 KB
  __shared__ float sm[LBL][5];              // padded means (bank-spread)
  __shared__ float scd[LBL], sss[LBL], sst[LBL];
  __shared__ float red[64];

  for (int i = tid; i < WARPS*LBL*32; i += NTHR){
    ((float*)s_val)[i] = 0.f; ((float*)s_cnt)[i] = 0.f;
  }
  if (tid < 32){
    int l = tid>>2, d = tid&3;
    float m = 0.f;
    if (l > 0) m = g_sumk[b][l][d] / fmaxf(g_cntk[b][l], 1.f);
    sm[l][d] = m;
  }
  if (tid < LBL){
    u64 v  = g_occ[b][tid];
    u32 f  = (u32)(v>>32); if (f  > (u32)(HW-1)) f  = HW-1;
    u32 s2 = (u32)v;       if (s2 > (u32)(HW-1)) s2 = HW-1;
    float r0 = (float)(f  / WD), c0 = (float)(f  % WD);
    float r1 = (float)(s2 / WD), c1 = (float)(s2 % WD);
    float dx = r0 - c0, dy = r1 - c1;
    scd[tid] = (tid > 0) ? __expf(__fsqrt_rn(dx*dx + dy*dy) * (0.5f/DIAG)) : 0.f;
    sss[tid] = r0 + c0;
    sst[tid] = r1 + c1;
  }
  __syncthreads();

  // block 0 of each image: l_dis + l_reg (tiny, fused former kC)
  if (blockIdx.x == 0 && tid < 64){
    int ii = tid>>3, jj = tid&7;
    float acc = 0.f;
    if (ii != jj && ii > 0 && jj > 0){
      float sq = 0.f;
      #pragma unroll
      for (int d = 0; d < EDIM; d++){ float dd = sm[ii][d]-sm[jj][d]; sq += dd*dd; }
      float Dn = __fsqrt_rn(sq);
      float dsp = sss[ii]-sss[jj], dtp = sst[ii]-sst[jj];
      float dp = __fsqrt_rn(dsp*dsp + dtp*dtp);
      float coef = 1.f - 20.f*__expf(-4.f - 2.5f*dp*(1.f/DIAG));
      float x = fmaxf(3.f - coef*Dn, 0.f);   // 2*DD
      acc = __logf(fmaf(x,x,1.f));
    }
    float reg = 0.f;
    if (tid < LBL){
      float sq = 0.f;
      #pragma unroll
      for (int d = 0; d < EDIM; d++) sq += sm[tid][d]*sm[tid][d];
      reg = __logf(__fsqrt_rn(sq) + 1.f);
    }
    red[tid] = acc*(1.f/42.f) + reg*(0.001f/8.f);
  }

  const float*  eb = emb + (size_t)b*EDIM*HW;
  const uchar4* lp = (const uchar4*)(g_lab + (size_t)b*HW);
  float* myval = &s_val[w][0][lane];   // + l*32
  float* mycnt = &s_cnt[w][0][lane];

  for (int i = blockIdx.x*NTHR + tid; i < NV4; i += gridDim.x*NTHR){
    uchar4 lv = lp[i];
    float4 e0 = ((const float4*)(eb        ))[i];
    float4 e1 = ((const float4*)(eb +   HW ))[i];
    float4 e2 = ((const float4*)(eb + 2*HW ))[i];
    float4 e3 = ((const float4*)(eb + 3*HW ))[i];

#define PROC_D(LV, E0, E1, E2, E3)                                          \
    if (LV > 0){                                                            \
      float d0 = E0 - sm[LV][0], d1 = E1 - sm[LV][1];                       \
      float d2 = E2 - sm[LV][2], d3 = E3 - sm[LV][3];                       \
      float sq = d0*d0 + d1*d1 + d2*d2 + d3*d3;                             \
      float x  = fmaxf(scd[LV]*__fsqrt_rn(sq) - 0.5f, 0.f);                 \
      myval[LV*32] += __logf(fmaf(x,x,1.f));                                \
      mycnt[LV*32] += 1.f;                                                  \
    }
    { int l = lv.x; PROC_D(l, e0.x, e1.x, e2.x, e3.x) }
    { int l = lv.y; PROC_D(l, e0.y, e1.y, e2.y, e3.y) }
    { int l = lv.z; PROC_D(l, e0.z, e1.z, e2.z, e3.z) }
    { int l = lv.w; PROC_D(l, e0.w, e1.w, e2.w, e3.w) }
#undef PROC_D
  }
  __syncthreads();

  if (blockIdx.x == 0 && tid < 32){
    float v = red[tid] + red[tid+32];
    #pragma unroll
    for (int o = 16; o > 0; o >>= 1) v += __shfl_down_sync(0xffffffffu, v, o);
    if (tid == 0) g_dr[b] = v;
  }
  if (tid < 64){
    int rw = tid>>3, rl = tid&7;
    float sv = 0.f, sc = 0.f;
    #pragma unroll
    for (int k = 0; k < 32; k++){
      int ln = (k+tid)&31;
      sv += s_val[rw][rl][ln];
      sc += s_cnt[rw][rl][ln];
    }
    if (rl > 0 && sc != 0.f){
      atomicAdd(&g_agg [b][rl], sv);
      atomicAdd(&g_cntf[b][rl], sc);
    }
  }
}

// ---------------- finalize ----------------
__global__ void kE(float* __restrict__ out){
  const int tid = threadIdx.x;
  __shared__ float red[BATCH];
  if (tid < BATCH){
    float s = 0.f;
    #pragma unroll
    for (int l = 1; l < LBL; l++)
      s += g_agg[tid][l] / fmaxf(g_cntf[tid][l], 1.f);
    red[tid] = s*(1.f/7.f) + g_dr[tid];
  }
  __syncthreads();
  if (tid == 0){
    float t = 0.f;
    #pragma unroll
    for (int b = 0; b < BATCH; b++) t += red[b];
    out[0] = t*(1.f/BATCH);
  }
}

extern "C" void kernel_launch(void* const* d_in, const int* in_sizes, int n_in,
                              void* d_out, int out_size){
  const float* emb   = (const float*)d_in[0];
  const int*   inst  = (const int*)  d_in[1];
  const float* kern  = (const float*)d_in[2];
  const float* tmask = (const float*)d_in[3];
  // d_in[4] = bboxes, unused

  k_init<<<1, 256>>>();
  kA<<<dim3(128, BATCH), NTHR>>>(emb, inst, kern, tmask);
  kD<<<dim3(128, BATCH), NTHR>>>(emb);
  kE<<<1, 32>>>((float*)d_out);
}